// round 15
// baseline (speedup 1.0000x reference)
#include <cuda_runtime.h>
#include <cuda_bf16.h>
#include <math.h>
#include <stdint.h>

#define T_LEN  4096
#define HIDDEN 2048
#define QH     16
#define KVH    4
#define HD     128
#define WINDOW 512
#define NC     3072   // fused QKV output width: 2048 + 512 + 512

// ---------------- device scratch (no cudaMalloc allowed) -------------------
__device__ float g_qkv[(size_t)T_LEN * NC];

__device__ __nv_bfloat16 g_xh[(size_t)T_LEN * HIDDEN];
__device__ __nv_bfloat16 g_xl[(size_t)T_LEN * HIDDEN];
__device__ __nv_bfloat16 g_wch[(size_t)NC * HIDDEN];     // concat wq|wk|wv hi
__device__ __nv_bfloat16 g_wcl[(size_t)NC * HIDDEN];     // concat wq|wk|wv lo
__device__ __nv_bfloat16 g_woh[(size_t)HIDDEN * QH * HD];
__device__ __nv_bfloat16 g_wol[(size_t)HIDDEN * QH * HD];

__device__ __nv_bfloat16 g_qh[(size_t)T_LEN * QH * HD];
__device__ __nv_bfloat16 g_ql[(size_t)T_LEN * QH * HD];
__device__ __nv_bfloat16 g_kh[(size_t)T_LEN * KVH * HD];
__device__ __nv_bfloat16 g_kl[(size_t)T_LEN * KVH * HD];
__device__ __nv_bfloat16 g_vh[(size_t)T_LEN * KVH * HD];
__device__ __nv_bfloat16 g_vl[(size_t)T_LEN * KVH * HD];
__device__ __nv_bfloat16 g_atth[(size_t)T_LEN * QH * HD];
__device__ __nv_bfloat16 g_attl[(size_t)T_LEN * QH * HD];

// ---------------------------------------------------------------------------
// helpers
// ---------------------------------------------------------------------------
__device__ __forceinline__ void ldm_x4(uint32_t* r, uint32_t addr)
{
    asm volatile("ldmatrix.sync.aligned.m8n8.x4.shared.b16 {%0,%1,%2,%3}, [%4];\n"
        : "=r"(r[0]), "=r"(r[1]), "=r"(r[2]), "=r"(r[3]) : "r"(addr));
}
__device__ __forceinline__ void ldm_x4_t(uint32_t* r, uint32_t addr)
{
    asm volatile("ldmatrix.sync.aligned.m8n8.x4.trans.shared.b16 {%0,%1,%2,%3}, [%4];\n"
        : "=r"(r[0]), "=r"(r[1]), "=r"(r[2]), "=r"(r[3]) : "r"(addr));
}
__device__ __forceinline__ void mma_bf16(float* d, const uint32_t* a, const uint32_t* b)
{
    asm volatile(
        "mma.sync.aligned.m16n8k16.row.col.f32.bf16.bf16.f32 "
        "{%0,%1,%2,%3}, {%4,%5,%6,%7}, {%8,%9}, {%0,%1,%2,%3};\n"
        : "+f"(d[0]), "+f"(d[1]), "+f"(d[2]), "+f"(d[3])
        : "r"(a[0]), "r"(a[1]), "r"(a[2]), "r"(a[3]), "r"(b[0]), "r"(b[1]));
}
__device__ __forceinline__ void pack_hilo(float a, float b, uint32_t& hi, uint32_t& lo)
{
    __nv_bfloat16 ha = __float2bfloat16(a);
    __nv_bfloat16 hb = __float2bfloat16(b);
    __nv_bfloat162 h2 = __halves2bfloat162(ha, hb);
    __nv_bfloat162 l2 = __halves2bfloat162(__float2bfloat16(a - __bfloat162float(ha)),
                                           __float2bfloat16(b - __bfloat162float(hb)));
    hi = *reinterpret_cast<uint32_t*>(&h2);
    lo = *reinterpret_cast<uint32_t*>(&l2);
}
__device__ __forceinline__ void split_store(float4 v, __nv_bfloat16* hi,
                                            __nv_bfloat16* lo, size_t d2)
{
    __nv_bfloat16 h0 = __float2bfloat16(v.x);
    __nv_bfloat16 h1 = __float2bfloat16(v.y);
    __nv_bfloat16 h2 = __float2bfloat16(v.z);
    __nv_bfloat16 h3 = __float2bfloat16(v.w);
    reinterpret_cast<__nv_bfloat162*>(hi)[d2]     = __halves2bfloat162(h0, h1);
    reinterpret_cast<__nv_bfloat162*>(hi)[d2 + 1] = __halves2bfloat162(h2, h3);
    reinterpret_cast<__nv_bfloat162*>(lo)[d2]     = __halves2bfloat162(
        __float2bfloat16(v.x - __bfloat162float(h0)),
        __float2bfloat16(v.y - __bfloat162float(h1)));
    reinterpret_cast<__nv_bfloat162*>(lo)[d2 + 1] = __halves2bfloat162(
        __float2bfloat16(v.z - __bfloat162float(h2)),
        __float2bfloat16(v.w - __bfloat162float(h3)));
}

// ---------------------------------------------------------------------------
// Fused split of x AND wq|wk|wv (one launch)
// ---------------------------------------------------------------------------
__global__ void split_xw_kernel(const float* __restrict__ x,
                                const float* __restrict__ wq,
                                const float* __restrict__ wk,
                                const float* __restrict__ wv,
                                __nv_bfloat16* __restrict__ xh, __nv_bfloat16* __restrict__ xl,
                                __nv_bfloat16* __restrict__ wch, __nv_bfloat16* __restrict__ wcl)
{
    const int N4X = T_LEN * HIDDEN / 4;
    const int N4Q = QH * HD * HIDDEN / 4;
    const int N4K = KVH * HD * HIDDEN / 4;
    int i = blockIdx.x * blockDim.x + threadIdx.x;
    if (i < N4X) {
        float4 v = reinterpret_cast<const float4*>(x)[i];
        split_store(v, xh, xl, (size_t)2 * i);
    } else {
        int j = i - N4X;
        if (j < N4Q + 2 * N4K) {
            const float* src; int o;
            if (j < N4Q)            { src = wq; o = j; }
            else if (j < N4Q + N4K) { src = wk; o = j - N4Q; }
            else                    { src = wv; o = j - N4Q - N4K; }
            float4 v = reinterpret_cast<const float4*>(src)[o];
            split_store(v, wch, wcl, (size_t)2 * j);
        }
    }
}

// plain contiguous split (wo)
__global__ void split_kernel(const float* __restrict__ src,
                             __nv_bfloat16* __restrict__ hi,
                             __nv_bfloat16* __restrict__ lo, int n4)
{
    int i = blockIdx.x * blockDim.x + threadIdx.x;
    if (i >= n4) return;
    float4 v = reinterpret_cast<const float4*>(src)[i];
    split_store(v, hi, lo, (size_t)2 * i);
}

// ---------------------------------------------------------------------------
// Fused: RoPE+split for q,k AND plain split for v (one launch)
// ---------------------------------------------------------------------------
__global__ void rope_v_kernel(const float* __restrict__ qkv,
                              __nv_bfloat16* __restrict__ qh, __nv_bfloat16* __restrict__ ql,
                              __nv_bfloat16* __restrict__ kh, __nv_bfloat16* __restrict__ kl,
                              __nv_bfloat16* __restrict__ vh, __nv_bfloat16* __restrict__ vl)
{
    const int NH = QH + KVH;   // 20
    const int ROPE_TOT = T_LEN * NH * (HD / 2);
    int idx = blockIdx.x * blockDim.x + threadIdx.x;
    if (idx < ROPE_TOT) {
        int i  = idx & 63;
        int hh = (idx >> 6) % NH;
        int t  = idx / (64 * NH);
        float inv = powf(10000.0f, -(float)i / 64.0f);
        float f = (float)t * inv;
        float c = cosf(f), s = sinf(f);
        bool isq = (hh < QH);
        int h = isq ? hh : hh - QH;
        float scale = isq ? 0.08838834764831845f : 1.0f;
        size_t sbase = (size_t)t * NC + (isq ? 0 : QH * HD) + (size_t)h * HD;
        __nv_bfloat16* hi = isq ? qh : kh;
        __nv_bfloat16* lo = isq ? ql : kl;
        size_t dbase = (size_t)t * (isq ? QH : KVH) * HD + (size_t)h * HD;
        float x1 = qkv[sbase + i];
        float x2 = qkv[sbase + i + 64];
        float y1 = (x1 * c - x2 * s) * scale;
        float y2 = (x1 * s + x2 * c) * scale;
        __nv_bfloat16 h1 = __float2bfloat16(y1);
        __nv_bfloat16 h2 = __float2bfloat16(y2);
        hi[dbase + i]      = h1;
        hi[dbase + i + 64] = h2;
        lo[dbase + i]      = __float2bfloat16(y1 - __bfloat162float(h1));
        lo[dbase + i + 64] = __float2bfloat16(y2 - __bfloat162float(h2));
    } else {
        int j = idx - ROPE_TOT;
        const int N4V = T_LEN * KVH * HD / 4;
        if (j < N4V) {
            const int cpr = KVH * HD / 4;   // 128
            int r = j / cpr, c4 = j % cpr;
            float4 v = *reinterpret_cast<const float4*>(
                qkv + (size_t)r * NC + (QH + KVH) * HD + c4 * 4);
            split_store(v, vh, vl, ((size_t)r * KVH * HD + c4 * 4) >> 1);
        }
    }
}

// ---------------------------------------------------------------------------
// bf16x3 tensor-core GEMM: C[M,N] = A[M,K] * B[N,K]^T (fp32 accum)
// CTA 128x128, BK=32, 3-stage cp.async, 256 threads, 2 CTAs/SM.
// Cross-barrier fragment prefetch: wait+sync at END of kt, then prefetch the
// next chunk's B-fragments + first A-half while tensor pipe drains.
// ---------------------------------------------------------------------------
#define GSTAGE 32768

__global__ __launch_bounds__(256, 2) void gemm_bf16x3(
    const __nv_bfloat16* __restrict__ Ah, const __nv_bfloat16* __restrict__ Al,
    const __nv_bfloat16* __restrict__ Bh, const __nv_bfloat16* __restrict__ Bl,
    float* __restrict__ C, int M, int N, int K)
{
    extern __shared__ char smem[];
    const int tid  = threadIdx.x;
    const int lane = tid & 31;
    const int warp = tid >> 5;
    const int wm   = warp >> 2;
    const int wn   = warp & 3;

    const __nv_bfloat16* Abh = Ah + (size_t)blockIdx.y * 128 * K;
    const __nv_bfloat16* Abl = Al + (size_t)blockIdx.y * 128 * K;
    const __nv_bfloat16* Bbh = Bh + (size_t)blockIdx.x * 128 * K;
    const __nv_bfloat16* Bbl = Bl + (size_t)blockIdx.x * 128 * K;

    const uint32_t smem_base = (uint32_t)__cvta_generic_to_shared(smem);

    float acc[4][4][4];
#pragma unroll
    for (int i = 0; i < 4; ++i)
#pragma unroll
        for (int j = 0; j < 4; ++j)
#pragma unroll
            for (int c = 0; c < 4; ++c) acc[i][j][c] = 0.f;

    auto load_stage = [&](int s, int k0) {
#pragma unroll
        for (int i = 0; i < 8; ++i) {
            const __nv_bfloat16* gb = (i < 2) ? Abh : (i < 4) ? Abl : (i < 6) ? Bbh : Bbl;
            int arr = i >> 1;
            int idx = ((i & 1) << 8) + tid;
            int r = idx >> 2, u = idx & 3;
            uint32_t dst = smem_base + s * GSTAGE + arr * 8192 +
                           (((r << 2) + (u ^ ((r >> 1) & 3))) << 4);
            const void* src = gb + (size_t)r * K + k0 + u * 8;
            asm volatile("cp.async.cg.shared.global [%0], [%1], 16;\n" :: "r"(dst), "l"(src));
        }
        asm volatile("cp.async.commit_group;\n");
    };

    // function-scope fragment buffers (reused across kk / kt — no extra regs)
    uint32_t bh[4][2], bl[4][2], ah[2][4], al[2][4];

    auto load_B = [&](uint32_t st, int kk) {
#pragma unroll
        for (int p = 0; p < 2; ++p) {
            int row = wn * 32 + p * 16 + ((lane >> 4) & 1) * 8 + (lane & 7);
            int u   = kk * 2 + ((lane >> 3) & 1);
            uint32_t off = ((row << 2) + (u ^ ((row >> 1) & 3))) << 4;
            uint32_t t0[4], t1[4];
            ldm_x4(t0, st + 16384 + off);
            bh[p * 2][0] = t0[0]; bh[p * 2][1] = t0[1];
            bh[p * 2 + 1][0] = t0[2]; bh[p * 2 + 1][1] = t0[3];
            ldm_x4(t1, st + 24576 + off);
            bl[p * 2][0] = t1[0]; bl[p * 2][1] = t1[1];
            bl[p * 2 + 1][0] = t1[2]; bl[p * 2 + 1][1] = t1[3];
        }
    };
    auto load_Ahalf = [&](uint32_t st, int kk, int mth) {
#pragma unroll
        for (int mt2 = 0; mt2 < 2; ++mt2) {
            int mt = mth * 2 + mt2;
            int row = wm * 64 + mt * 16 + ((lane >> 3) & 1) * 8 + (lane & 7);
            int u   = kk * 2 + (lane >> 4);
            uint32_t off = ((row << 2) + (u ^ ((row >> 1) & 3))) << 4;
            ldm_x4(ah[mt2], st + off);
            ldm_x4(al[mt2], st + 8192 + off);
        }
    };
    auto mma_half = [&](int mth) {
#pragma unroll
        for (int mt2 = 0; mt2 < 2; ++mt2)
#pragma unroll
            for (int nt = 0; nt < 4; ++nt) {
                float* d = acc[mth * 2 + mt2][nt];
                mma_bf16(d, ah[mt2], bh[nt]);
                mma_bf16(d, ah[mt2], bl[nt]);
                mma_bf16(d, al[mt2], bh[nt]);
            }
    };

    const int KT = K >> 5;
    load_stage(0, 0);
    load_stage(1, 32);
    asm volatile("cp.async.wait_group 1;\n");
    __syncthreads();
    uint32_t st = smem_base;            // stage 0
    load_B(st, 0);
    load_Ahalf(st, 0, 0);

    for (int kt = 0; kt < KT; ++kt) {
        if (kt + 2 < KT) load_stage((kt + 2) % 3, (kt + 2) << 5);
        // kk = 0 (B + A-half0 prefetched)
        mma_half(0);
        load_Ahalf(st, 0, 1);
        mma_half(1);
        load_B(st, 1);
        load_Ahalf(st, 1, 0);
        // kk = 1
        mma_half(0);
        load_Ahalf(st, 1, 1);
        mma_half(1);
        // boundary: wait for next stage, barrier, prefetch next chunk's frags
        if (kt + 1 < KT) {
            if (kt + 2 < KT) { asm volatile("cp.async.wait_group 1;\n"); }
            else             { asm volatile("cp.async.wait_group 0;\n"); }
            __syncthreads();
            st = smem_base + ((kt + 1) % 3) * GSTAGE;
            load_B(st, 0);
            load_Ahalf(st, 0, 0);
        }
    }

    const int grp = lane >> 2, tig = lane & 3;
#pragma unroll
    for (int mt = 0; mt < 4; ++mt)
#pragma unroll
        for (int nt = 0; nt < 4; ++nt) {
            int r0 = blockIdx.y * 128 + wm * 64 + mt * 16 + grp;
            int c0 = blockIdx.x * 128 + wn * 32 + nt * 8 + tig * 2;
            float2 v0 = make_float2(acc[mt][nt][0], acc[mt][nt][1]);
            float2 v1 = make_float2(acc[mt][nt][2], acc[mt][nt][3]);
            *reinterpret_cast<float2*>(&C[(size_t)r0 * N + c0])       = v0;
            *reinterpret_cast<float2*>(&C[(size_t)(r0 + 8) * N + c0]) = v1;
        }
}

// ---------------------------------------------------------------------------
// Tensor-core flash attention (bf16x3 for QK^T and PV) — unchanged
// ---------------------------------------------------------------------------
#define AT_STAGE 32768

__global__ __launch_bounds__(128) void attn_mma(
    const __nv_bfloat16* __restrict__ Qh, const __nv_bfloat16* __restrict__ Ql,
    const __nv_bfloat16* __restrict__ Kh, const __nv_bfloat16* __restrict__ Kl,
    const __nv_bfloat16* __restrict__ Vh, const __nv_bfloat16* __restrict__ Vl,
    __nv_bfloat16* __restrict__ Oh, __nv_bfloat16* __restrict__ Ol)
{
    extern __shared__ char smem[];
    const uint32_t sb = (uint32_t)__cvta_generic_to_shared(smem);
    const int tid = threadIdx.x, lane = tid & 31, w = tid >> 5;
    const int h = blockIdx.y, g = h >> 2;
    const int qt0 = blockIdx.x * 64;
    const int grp = lane >> 2, tig = lane & 3;
    const int row0 = qt0 + w * 16 + grp;

    uint32_t qfh[8][4], qfl[8][4];
#pragma unroll
    for (int c = 0; c < 8; ++c) {
        int d0 = 16 * c + 2 * tig;
        size_t b0 = ((size_t)row0 * QH + h) * HD;
        size_t b1 = ((size_t)(row0 + 8) * QH + h) * HD;
        qfh[c][0] = *reinterpret_cast<const uint32_t*>(Qh + b0 + d0);
        qfh[c][1] = *reinterpret_cast<const uint32_t*>(Qh + b1 + d0);
        qfh[c][2] = *reinterpret_cast<const uint32_t*>(Qh + b0 + d0 + 8);
        qfh[c][3] = *reinterpret_cast<const uint32_t*>(Qh + b1 + d0 + 8);
        qfl[c][0] = *reinterpret_cast<const uint32_t*>(Ql + b0 + d0);
        qfl[c][1] = *reinterpret_cast<const uint32_t*>(Ql + b1 + d0);
        qfl[c][2] = *reinterpret_cast<const uint32_t*>(Ql + b0 + d0 + 8);
        qfl[c][3] = *reinterpret_cast<const uint32_t*>(Ql + b1 + d0 + 8);
    }

    float o[16][4];
#pragma unroll
    for (int n = 0; n < 16; ++n)
#pragma unroll
        for (int j = 0; j < 4; ++j) o[n][j] = 0.f;
    float m0 = -1e30f, m1 = -1e30f, l0 = 0.f, l1 = 0.f;

    int s_lo = qt0 - WINDOW; if (s_lo < 0) s_lo = 0;
    const int n_tiles = (qt0 + 64 - s_lo) / 32;

    auto load_stage = [&](int st, int s0) {
#pragma unroll
        for (int j = 0; j < 16; ++j) {
            int i = tid + 128 * j;
            int arr = i >> 9;
            int rem = i & 511;
            int r = rem >> 4, u = rem & 15;
            const __nv_bfloat16* gp =
                (arr == 0 ? Kh : arr == 1 ? Kl : arr == 2 ? Vh : Vl) +
                ((size_t)(s0 + r) * KVH + g) * HD + u * 8;
            uint32_t dst = sb + st * AT_STAGE + arr * 8192 + r * 256 + ((u ^ (r & 7)) << 4);
            asm volatile("cp.async.cg.shared.global [%0], [%1], 16;\n" :: "r"(dst), "l"(gp));
        }
        asm volatile("cp.async.commit_group;\n");
    };

    load_stage(0, s_lo);

    for (int tile = 0; tile < n_tiles; ++tile) {
        const int s0 = s_lo + tile * 32;
        if (tile + 1 < n_tiles) {
            load_stage((tile + 1) & 1, s0 + 32);
            asm volatile("cp.async.wait_group 1;\n");
        } else {
            asm volatile("cp.async.wait_group 0;\n");
        }
        __syncthreads();

        const uint32_t st = sb + (tile & 1) * AT_STAGE;

        float S[4][4];
#pragma unroll
        for (int n = 0; n < 4; ++n)
#pragma unroll
            for (int j = 0; j < 4; ++j) S[n][j] = 0.f;

#pragma unroll
        for (int c = 0; c < 8; ++c) {
            uint32_t kh[2][4], kl[2][4];
#pragma unroll
            for (int p = 0; p < 2; ++p) {
                int row = p * 16 + (lane & 7) + 8 * ((lane >> 3) & 1);
                int u   = 2 * c + (lane >> 4);
                uint32_t off = row * 256 + ((u ^ (row & 7)) << 4);
                ldm_x4(kh[p], st + off);
                ldm_x4(kl[p], st + 8192 + off);
            }
#pragma unroll
            for (int n = 0; n < 4; ++n) {
                uint32_t bh[2] = { kh[n >> 1][n & 1], kh[n >> 1][(n & 1) + 2] };
                uint32_t bl[2] = { kl[n >> 1][n & 1], kl[n >> 1][(n & 1) + 2] };
                mma_bf16(S[n], qfh[c], bh);
                mma_bf16(S[n], qfh[c], bl);
                mma_bf16(S[n], qfl[c], bh);
            }
        }

        bool causal_safe = (s0 + 31 <= qt0 + 16 * w);
        bool window_safe = (s0 >= qt0 + 16 * w + 15 - WINDOW);
        if (!(causal_safe && window_safe)) {
#pragma unroll
            for (int n = 0; n < 4; ++n)
#pragma unroll
                for (int j = 0; j < 4; ++j) {
                    int s = s0 + 8 * n + 2 * tig + (j & 1);
                    int t = (j < 2) ? row0 : row0 + 8;
                    bool ok = (s <= t) && (t - s <= WINDOW);
                    if (!ok) S[n][j] = -1e30f;
                }
        }

        float mx0 = -1e30f, mx1 = -1e30f;
#pragma unroll
        for (int n = 0; n < 4; ++n) {
            mx0 = fmaxf(mx0, fmaxf(S[n][0], S[n][1]));
            mx1 = fmaxf(mx1, fmaxf(S[n][2], S[n][3]));
        }
        mx0 = fmaxf(mx0, __shfl_xor_sync(0xffffffffu, mx0, 1));
        mx0 = fmaxf(mx0, __shfl_xor_sync(0xffffffffu, mx0, 2));
        mx1 = fmaxf(mx1, __shfl_xor_sync(0xffffffffu, mx1, 1));
        mx1 = fmaxf(mx1, __shfl_xor_sync(0xffffffffu, mx1, 2));

        float mn0 = fmaxf(m0, mx0), mn1 = fmaxf(m1, mx1);
        float fac0 = __expf(m0 - mn0), fac1 = __expf(m1 - mn1);
        m0 = mn0; m1 = mn1;

        float rs0 = 0.f, rs1 = 0.f;
#pragma unroll
        for (int n = 0; n < 4; ++n) {
            S[n][0] = __expf(S[n][0] - mn0);
            S[n][1] = __expf(S[n][1] - mn0);
            S[n][2] = __expf(S[n][2] - mn1);
            S[n][3] = __expf(S[n][3] - mn1);
            rs0 += S[n][0] + S[n][1];
            rs1 += S[n][2] + S[n][3];
        }
        rs0 += __shfl_xor_sync(0xffffffffu, rs0, 1);
        rs0 += __shfl_xor_sync(0xffffffffu, rs0, 2);
        rs1 += __shfl_xor_sync(0xffffffffu, rs1, 1);
        rs1 += __shfl_xor_sync(0xffffffffu, rs1, 2);
        l0 = l0 * fac0 + rs0;
        l1 = l1 * fac1 + rs1;

#pragma unroll
        for (int n = 0; n < 16; ++n) {
            o[n][0] *= fac0; o[n][1] *= fac0;
            o[n][2] *= fac1; o[n][3] *= fac1;
        }

#pragma unroll
        for (int kc = 0; kc < 2; ++kc) {
            int j0 = 2 * kc, j1 = 2 * kc + 1;
            uint32_t pah[4], pal[4];
            pack_hilo(S[j0][0], S[j0][1], pah[0], pal[0]);
            pack_hilo(S[j0][2], S[j0][3], pah[1], pal[1]);
            pack_hilo(S[j1][0], S[j1][1], pah[2], pal[2]);
            pack_hilo(S[j1][2], S[j1][3], pah[3], pal[3]);
#pragma unroll
            for (int dp = 0; dp < 8; ++dp) {
                int row = kc * 16 + (lane & 7) + 8 * ((lane >> 3) & 1);
                int u   = 2 * dp + (lane >> 4);
                uint32_t off = row * 256 + ((u ^ (row & 7)) << 4);
                uint32_t vh[4], vl[4];
                ldm_x4_t(vh, st + 16384 + off);
                ldm_x4_t(vl, st + 24576 + off);
                uint32_t bh0[2] = { vh[0], vh[1] }, bh1[2] = { vh[2], vh[3] };
                uint32_t bl0[2] = { vl[0], vl[1] }, bl1[2] = { vl[2], vl[3] };
                mma_bf16(o[2 * dp],     pah, bh0);
                mma_bf16(o[2 * dp],     pah, bl0);
                mma_bf16(o[2 * dp],     pal, bh0);
                mma_bf16(o[2 * dp + 1], pah, bh1);
                mma_bf16(o[2 * dp + 1], pah, bl1);
                mma_bf16(o[2 * dp + 1], pal, bh1);
            }
        }
        __syncthreads();
    }

    float inv0 = 1.0f / l0, inv1 = 1.0f / l1;
#pragma unroll
    for (int n = 0; n < 16; ++n) {
        int d = 8 * n + 2 * tig;
        float a0 = o[n][0] * inv0, a1 = o[n][1] * inv0;
        float b0 = o[n][2] * inv1, b1 = o[n][3] * inv1;
        uint32_t h0, lo0, h1, lo1;
        pack_hilo(a0, a1, h0, lo0);
        pack_hilo(b0, b1, h1, lo1);
        size_t p0 = ((size_t)row0 * QH + h) * HD + d;
        size_t p1 = ((size_t)(row0 + 8) * QH + h) * HD + d;
        *reinterpret_cast<uint32_t*>(Oh + p0) = h0;
        *reinterpret_cast<uint32_t*>(Ol + p0) = lo0;
        *reinterpret_cast<uint32_t*>(Oh + p1) = h1;
        *reinterpret_cast<uint32_t*>(Ol + p1) = lo1;
    }
}

// ---------------------------------------------------------------------------
extern "C" void kernel_launch(void* const* d_in, const int* in_sizes, int n_in,
                              void* d_out, int out_size)
{
    const float* x  = (const float*)d_in[0];
    const float* wq = (const float*)d_in[1];
    const float* wk = (const float*)d_in[2];
    const float* wv = (const float*)d_in[3];
    const float* wo = (const float*)d_in[4];
    float* out = (float*)d_out;

    float* qkv;
    cudaGetSymbolAddress((void**)&qkv, g_qkv);

    __nv_bfloat16 *xh, *xl, *wch, *wcl, *woh, *wol;
    __nv_bfloat16 *qh, *ql, *kh, *kl, *vh, *vl, *atth, *attl;
    cudaGetSymbolAddress((void**)&xh,  g_xh);   cudaGetSymbolAddress((void**)&xl,  g_xl);
    cudaGetSymbolAddress((void**)&wch, g_wch);  cudaGetSymbolAddress((void**)&wcl, g_wcl);
    cudaGetSymbolAddress((void**)&woh, g_woh);  cudaGetSymbolAddress((void**)&wol, g_wol);
    cudaGetSymbolAddress((void**)&qh,  g_qh);   cudaGetSymbolAddress((void**)&ql,  g_ql);
    cudaGetSymbolAddress((void**)&kh,  g_kh);   cudaGetSymbolAddress((void**)&kl,  g_kl);
    cudaGetSymbolAddress((void**)&vh,  g_vh);   cudaGetSymbolAddress((void**)&vl,  g_vl);
    cudaGetSymbolAddress((void**)&atth, g_atth); cudaGetSymbolAddress((void**)&attl, g_attl);

    cudaFuncSetAttribute(gemm_bf16x3, cudaFuncAttributeMaxDynamicSharedMemorySize, 3 * GSTAGE);
    cudaFuncSetAttribute(attn_mma,    cudaFuncAttributeMaxDynamicSharedMemorySize, 2 * AT_STAGE);

    // #1: fused split of x and wq|wk|wv
    {
        int tot = T_LEN * HIDDEN / 4 + NC * HIDDEN / 4;
        split_xw_kernel<<<(tot + 255) / 256, 256>>>(x, wq, wk, wv, xh, xl, wch, wcl);
    }
    // #2: fused QKV projection
    gemm_bf16x3<<<dim3(NC / 128, T_LEN / 128), 256, 3 * GSTAGE>>>(
        xh, xl, wch, wcl, qkv, T_LEN, NC, HIDDEN);
    // #3: fused RoPE+split (q,k) and V split
    {
        int tot = T_LEN * (QH + KVH) * (HD / 2) + T_LEN * KVH * HD / 4;
        rope_v_kernel<<<(tot + 255) / 256, 256>>>(qkv, qh, ql, kh, kl, vh, vl);
    }
    // #4: tensor-core attention (profiling slot)
    attn_mma<<<dim3(T_LEN / 64, QH), 128, 2 * AT_STAGE>>>(
        qh, ql, kh, kl, vh, vl, atth, attl);
    // #5: split wo (independent of attention; placed late to keep attn at #4)
    {
        int n4 = HIDDEN * QH * HD / 4;
        split_kernel<<<(n4 + 255) / 256, 256>>>(wo, woh, wol, n4);
    }
    // #6: output projection
    gemm_bf16x3<<<dim3(HIDDEN / 128, T_LEN / 128), 256, 3 * GSTAGE>>>(
        atth, attl, woh, wol, out, T_LEN, HIDDEN, QH * HD);
}

// round 17
// speedup vs baseline: 1.0331x; 1.0331x over previous
#include <cuda_runtime.h>
#include <cuda_bf16.h>
#include <math.h>
#include <stdint.h>

#define T_LEN  4096
#define HIDDEN 2048
#define QH     16
#define KVH    4
#define HD     128
#define WINDOW 512
#define NC     3072   // fused QKV output width: 2048 + 512 + 512

// ---------------- device scratch (no cudaMalloc allowed) -------------------
__device__ float g_qkv[(size_t)T_LEN * NC];

__device__ __nv_bfloat16 g_xh[(size_t)T_LEN * HIDDEN];
__device__ __nv_bfloat16 g_xl[(size_t)T_LEN * HIDDEN];
__device__ __nv_bfloat16 g_wch[(size_t)NC * HIDDEN];     // concat wq|wk|wv hi
__device__ __nv_bfloat16 g_wcl[(size_t)NC * HIDDEN];     // concat wq|wk|wv lo
__device__ __nv_bfloat16 g_woh[(size_t)HIDDEN * QH * HD];
__device__ __nv_bfloat16 g_wol[(size_t)HIDDEN * QH * HD];

__device__ __nv_bfloat16 g_qh[(size_t)T_LEN * QH * HD];
__device__ __nv_bfloat16 g_ql[(size_t)T_LEN * QH * HD];
__device__ __nv_bfloat16 g_kh[(size_t)T_LEN * KVH * HD];
__device__ __nv_bfloat16 g_kl[(size_t)T_LEN * KVH * HD];
__device__ __nv_bfloat16 g_vh[(size_t)T_LEN * KVH * HD];
__device__ __nv_bfloat16 g_vl[(size_t)T_LEN * KVH * HD];
__device__ __nv_bfloat16 g_atth[(size_t)T_LEN * QH * HD];
__device__ __nv_bfloat16 g_attl[(size_t)T_LEN * QH * HD];

// ---------------------------------------------------------------------------
// helpers
// ---------------------------------------------------------------------------
__device__ __forceinline__ void ldm_x4(uint32_t* r, uint32_t addr)
{
    asm volatile("ldmatrix.sync.aligned.m8n8.x4.shared.b16 {%0,%1,%2,%3}, [%4];\n"
        : "=r"(r[0]), "=r"(r[1]), "=r"(r[2]), "=r"(r[3]) : "r"(addr));
}
__device__ __forceinline__ void ldm_x4_t(uint32_t* r, uint32_t addr)
{
    asm volatile("ldmatrix.sync.aligned.m8n8.x4.trans.shared.b16 {%0,%1,%2,%3}, [%4];\n"
        : "=r"(r[0]), "=r"(r[1]), "=r"(r[2]), "=r"(r[3]) : "r"(addr));
}
__device__ __forceinline__ void mma_bf16(float* d, const uint32_t* a, const uint32_t* b)
{
    asm volatile(
        "mma.sync.aligned.m16n8k16.row.col.f32.bf16.bf16.f32 "
        "{%0,%1,%2,%3}, {%4,%5,%6,%7}, {%8,%9}, {%0,%1,%2,%3};\n"
        : "+f"(d[0]), "+f"(d[1]), "+f"(d[2]), "+f"(d[3])
        : "r"(a[0]), "r"(a[1]), "r"(a[2]), "r"(a[3]), "r"(b[0]), "r"(b[1]));
}
__device__ __forceinline__ void pack_hilo(float a, float b, uint32_t& hi, uint32_t& lo)
{
    __nv_bfloat16 ha = __float2bfloat16(a);
    __nv_bfloat16 hb = __float2bfloat16(b);
    __nv_bfloat162 h2 = __halves2bfloat162(ha, hb);
    __nv_bfloat162 l2 = __halves2bfloat162(__float2bfloat16(a - __bfloat162float(ha)),
                                           __float2bfloat16(b - __bfloat162float(hb)));
    hi = *reinterpret_cast<uint32_t*>(&h2);
    lo = *reinterpret_cast<uint32_t*>(&l2);
}
__device__ __forceinline__ void split_store(float4 v, __nv_bfloat16* hi,
                                            __nv_bfloat16* lo, size_t d2)
{
    __nv_bfloat16 h0 = __float2bfloat16(v.x);
    __nv_bfloat16 h1 = __float2bfloat16(v.y);
    __nv_bfloat16 h2 = __float2bfloat16(v.z);
    __nv_bfloat16 h3 = __float2bfloat16(v.w);
    reinterpret_cast<__nv_bfloat162*>(hi)[d2]     = __halves2bfloat162(h0, h1);
    reinterpret_cast<__nv_bfloat162*>(hi)[d2 + 1] = __halves2bfloat162(h2, h3);
    reinterpret_cast<__nv_bfloat162*>(lo)[d2]     = __halves2bfloat162(
        __float2bfloat16(v.x - __bfloat162float(h0)),
        __float2bfloat16(v.y - __bfloat162float(h1)));
    reinterpret_cast<__nv_bfloat162*>(lo)[d2 + 1] = __halves2bfloat162(
        __float2bfloat16(v.z - __bfloat162float(h2)),
        __float2bfloat16(v.w - __bfloat162float(h3)));
}

// ---------------------------------------------------------------------------
// Fused split of x AND wq|wk|wv (one launch)
// ---------------------------------------------------------------------------
__global__ void split_xw_kernel(const float* __restrict__ x,
                                const float* __restrict__ wq,
                                const float* __restrict__ wk,
                                const float* __restrict__ wv,
                                __nv_bfloat16* __restrict__ xh, __nv_bfloat16* __restrict__ xl,
                                __nv_bfloat16* __restrict__ wch, __nv_bfloat16* __restrict__ wcl)
{
    const int N4X = T_LEN * HIDDEN / 4;
    const int N4Q = QH * HD * HIDDEN / 4;
    const int N4K = KVH * HD * HIDDEN / 4;
    int i = blockIdx.x * blockDim.x + threadIdx.x;
    if (i < N4X) {
        float4 v = reinterpret_cast<const float4*>(x)[i];
        split_store(v, xh, xl, (size_t)2 * i);
    } else {
        int j = i - N4X;
        if (j < N4Q + 2 * N4K) {
            const float* src; int o;
            if (j < N4Q)            { src = wq; o = j; }
            else if (j < N4Q + N4K) { src = wk; o = j - N4Q; }
            else                    { src = wv; o = j - N4Q - N4K; }
            float4 v = reinterpret_cast<const float4*>(src)[o];
            split_store(v, wch, wcl, (size_t)2 * j);
        }
    }
}

// plain contiguous split (wo)
__global__ void split_kernel(const float* __restrict__ src,
                             __nv_bfloat16* __restrict__ hi,
                             __nv_bfloat16* __restrict__ lo, int n4)
{
    int i = blockIdx.x * blockDim.x + threadIdx.x;
    if (i >= n4) return;
    float4 v = reinterpret_cast<const float4*>(src)[i];
    split_store(v, hi, lo, (size_t)2 * i);
}

// ---------------------------------------------------------------------------
// Fused: RoPE+split for q,k AND plain split for v (one launch)
// ---------------------------------------------------------------------------
__global__ void rope_v_kernel(const float* __restrict__ qkv,
                              __nv_bfloat16* __restrict__ qh, __nv_bfloat16* __restrict__ ql,
                              __nv_bfloat16* __restrict__ kh, __nv_bfloat16* __restrict__ kl,
                              __nv_bfloat16* __restrict__ vh, __nv_bfloat16* __restrict__ vl)
{
    const int NH = QH + KVH;   // 20
    const int ROPE_TOT = T_LEN * NH * (HD / 2);
    int idx = blockIdx.x * blockDim.x + threadIdx.x;
    if (idx < ROPE_TOT) {
        int i  = idx & 63;
        int hh = (idx >> 6) % NH;
        int t  = idx / (64 * NH);
        float inv = powf(10000.0f, -(float)i / 64.0f);
        float f = (float)t * inv;
        float c = cosf(f), s = sinf(f);
        bool isq = (hh < QH);
        int h = isq ? hh : hh - QH;
        float scale = isq ? 0.08838834764831845f : 1.0f;
        size_t sbase = (size_t)t * NC + (isq ? 0 : QH * HD) + (size_t)h * HD;
        __nv_bfloat16* hi = isq ? qh : kh;
        __nv_bfloat16* lo = isq ? ql : kl;
        size_t dbase = (size_t)t * (isq ? QH : KVH) * HD + (size_t)h * HD;
        float x1 = qkv[sbase + i];
        float x2 = qkv[sbase + i + 64];
        float y1 = (x1 * c - x2 * s) * scale;
        float y2 = (x1 * s + x2 * c) * scale;
        __nv_bfloat16 h1 = __float2bfloat16(y1);
        __nv_bfloat16 h2 = __float2bfloat16(y2);
        hi[dbase + i]      = h1;
        hi[dbase + i + 64] = h2;
        lo[dbase + i]      = __float2bfloat16(y1 - __bfloat162float(h1));
        lo[dbase + i + 64] = __float2bfloat16(y2 - __bfloat162float(h2));
    } else {
        int j = idx - ROPE_TOT;
        const int N4V = T_LEN * KVH * HD / 4;
        if (j < N4V) {
            const int cpr = KVH * HD / 4;   // 128
            int r = j / cpr, c4 = j % cpr;
            float4 v = *reinterpret_cast<const float4*>(
                qkv + (size_t)r * NC + (QH + KVH) * HD + c4 * 4);
            split_store(v, vh, vl, ((size_t)r * KVH * HD + c4 * 4) >> 1);
        }
    }
}

// ---------------------------------------------------------------------------
// bf16x3 tensor-core GEMM — exact R14 schedule (known-good, 66% tensor).
// CTA 128x128, BK=32, 3-stage cp.async, 256 threads, 2 CTAs/SM.
// ---------------------------------------------------------------------------
#define GSTAGE 32768

__global__ __launch_bounds__(256, 2) void gemm_bf16x3(
    const __nv_bfloat16* __restrict__ Ah, const __nv_bfloat16* __restrict__ Al,
    const __nv_bfloat16* __restrict__ Bh, const __nv_bfloat16* __restrict__ Bl,
    float* __restrict__ C, int M, int N, int K)
{
    extern __shared__ char smem[];
    const int tid  = threadIdx.x;
    const int lane = tid & 31;
    const int warp = tid >> 5;
    const int wm   = warp >> 2;
    const int wn   = warp & 3;

    const __nv_bfloat16* Abh = Ah + (size_t)blockIdx.y * 128 * K;
    const __nv_bfloat16* Abl = Al + (size_t)blockIdx.y * 128 * K;
    const __nv_bfloat16* Bbh = Bh + (size_t)blockIdx.x * 128 * K;
    const __nv_bfloat16* Bbl = Bl + (size_t)blockIdx.x * 128 * K;

    const uint32_t smem_base = (uint32_t)__cvta_generic_to_shared(smem);

    float acc[4][4][4];
#pragma unroll
    for (int i = 0; i < 4; ++i)
#pragma unroll
        for (int j = 0; j < 4; ++j)
#pragma unroll
            for (int c = 0; c < 4; ++c) acc[i][j][c] = 0.f;

    auto load_stage = [&](int s, int k0) {
#pragma unroll
        for (int i = 0; i < 8; ++i) {
            const __nv_bfloat16* gb = (i < 2) ? Abh : (i < 4) ? Abl : (i < 6) ? Bbh : Bbl;
            int arr = i >> 1;
            int idx = ((i & 1) << 8) + tid;
            int r = idx >> 2, u = idx & 3;
            uint32_t dst = smem_base + s * GSTAGE + arr * 8192 +
                           (((r << 2) + (u ^ ((r >> 1) & 3))) << 4);
            const void* src = gb + (size_t)r * K + k0 + u * 8;
            asm volatile("cp.async.cg.shared.global [%0], [%1], 16;\n" :: "r"(dst), "l"(src));
        }
        asm volatile("cp.async.commit_group;\n");
    };

    const int KT = K >> 5;
    load_stage(0, 0);
    load_stage(1, 32);

    for (int kt = 0; kt < KT; ++kt) {
        if (kt + 1 < KT) { asm volatile("cp.async.wait_group 1;\n"); }
        else             { asm volatile("cp.async.wait_group 0;\n"); }
        __syncthreads();
        if (kt + 2 < KT) {
            int s = (kt + 2) % 3;
            load_stage(s, (kt + 2) << 5);
        }

        const uint32_t stA_h = smem_base + (kt % 3) * GSTAGE;
        const uint32_t stA_l = stA_h + 8192;
        const uint32_t stB_h = stA_h + 16384;
        const uint32_t stB_l = stA_h + 24576;

#pragma unroll
        for (int kk = 0; kk < 2; ++kk) {
            const int k0 = kk * 16;
            uint32_t bh[4][2], bl[4][2];
#pragma unroll
            for (int p = 0; p < 2; ++p) {
                int row = wn * 32 + p * 16 + ((lane >> 4) & 1) * 8 + (lane & 7);
                int u   = (k0 >> 3) + ((lane >> 3) & 1);
                uint32_t off = ((row << 2) + (u ^ ((row >> 1) & 3))) << 4;
                uint32_t t0[4], t1[4];
                ldm_x4(t0, stB_h + off);
                bh[p * 2][0] = t0[0]; bh[p * 2][1] = t0[1];
                bh[p * 2 + 1][0] = t0[2]; bh[p * 2 + 1][1] = t0[3];
                ldm_x4(t1, stB_l + off);
                bl[p * 2][0] = t1[0]; bl[p * 2][1] = t1[1];
                bl[p * 2 + 1][0] = t1[2]; bl[p * 2 + 1][1] = t1[3];
            }
#pragma unroll
            for (int mth = 0; mth < 2; ++mth) {
                uint32_t ah[2][4], al[2][4];
#pragma unroll
                for (int mt2 = 0; mt2 < 2; ++mt2) {
                    int mt = mth * 2 + mt2;
                    int row = wm * 64 + mt * 16 + ((lane >> 3) & 1) * 8 + (lane & 7);
                    int u   = (k0 >> 3) + (lane >> 4);
                    uint32_t off = ((row << 2) + (u ^ ((row >> 1) & 3))) << 4;
                    ldm_x4(ah[mt2], stA_h + off);
                    ldm_x4(al[mt2], stA_l + off);
                }
#pragma unroll
                for (int mt2 = 0; mt2 < 2; ++mt2)
#pragma unroll
                    for (int nt = 0; nt < 4; ++nt) {
                        float* d = acc[mth * 2 + mt2][nt];
                        mma_bf16(d, ah[mt2], bh[nt]);
                        mma_bf16(d, ah[mt2], bl[nt]);
                        mma_bf16(d, al[mt2], bh[nt]);
                    }
            }
        }
    }

    const int grp = lane >> 2, tig = lane & 3;
#pragma unroll
    for (int mt = 0; mt < 4; ++mt)
#pragma unroll
        for (int nt = 0; nt < 4; ++nt) {
            int r0 = blockIdx.y * 128 + wm * 64 + mt * 16 + grp;
            int c0 = blockIdx.x * 128 + wn * 32 + nt * 8 + tig * 2;
            float2 v0 = make_float2(acc[mt][nt][0], acc[mt][nt][1]);
            float2 v1 = make_float2(acc[mt][nt][2], acc[mt][nt][3]);
            *reinterpret_cast<float2*>(&C[(size_t)r0 * N + c0])       = v0;
            *reinterpret_cast<float2*>(&C[(size_t)(r0 + 8) * N + c0]) = v1;
        }
}

// ---------------------------------------------------------------------------
// Tensor-core flash attention + per-warp fully-masked-tile skip
// ---------------------------------------------------------------------------
#define AT_STAGE 32768

__global__ __launch_bounds__(128) void attn_mma(
    const __nv_bfloat16* __restrict__ Qh, const __nv_bfloat16* __restrict__ Ql,
    const __nv_bfloat16* __restrict__ Kh, const __nv_bfloat16* __restrict__ Kl,
    const __nv_bfloat16* __restrict__ Vh, const __nv_bfloat16* __restrict__ Vl,
    __nv_bfloat16* __restrict__ Oh, __nv_bfloat16* __restrict__ Ol)
{
    extern __shared__ char smem[];
    const uint32_t sb = (uint32_t)__cvta_generic_to_shared(smem);
    const int tid = threadIdx.x, lane = tid & 31, w = tid >> 5;
    const int h = blockIdx.y, g = h >> 2;
    const int qt0 = blockIdx.x * 64;
    const int grp = lane >> 2, tig = lane & 3;
    const int row0 = qt0 + w * 16 + grp;
    const int wrow_lo = qt0 + w * 16;          // warp's min query row
    const int wrow_hi = qt0 + w * 16 + 15;     // warp's max query row

    uint32_t qfh[8][4], qfl[8][4];
#pragma unroll
    for (int c = 0; c < 8; ++c) {
        int d0 = 16 * c + 2 * tig;
        size_t b0 = ((size_t)row0 * QH + h) * HD;
        size_t b1 = ((size_t)(row0 + 8) * QH + h) * HD;
        qfh[c][0] = *reinterpret_cast<const uint32_t*>(Qh + b0 + d0);
        qfh[c][1] = *reinterpret_cast<const uint32_t*>(Qh + b1 + d0);
        qfh[c][2] = *reinterpret_cast<const uint32_t*>(Qh + b0 + d0 + 8);
        qfh[c][3] = *reinterpret_cast<const uint32_t*>(Qh + b1 + d0 + 8);
        qfl[c][0] = *reinterpret_cast<const uint32_t*>(Ql + b0 + d0);
        qfl[c][1] = *reinterpret_cast<const uint32_t*>(Ql + b1 + d0);
        qfl[c][2] = *reinterpret_cast<const uint32_t*>(Ql + b0 + d0 + 8);
        qfl[c][3] = *reinterpret_cast<const uint32_t*>(Ql + b1 + d0 + 8);
    }

    float o[16][4];
#pragma unroll
    for (int n = 0; n < 16; ++n)
#pragma unroll
        for (int j = 0; j < 4; ++j) o[n][j] = 0.f;
    float m0 = -1e30f, m1 = -1e30f, l0 = 0.f, l1 = 0.f;

    int s_lo = qt0 - WINDOW; if (s_lo < 0) s_lo = 0;
    const int n_tiles = (qt0 + 64 - s_lo) / 32;

    auto load_stage = [&](int st, int s0) {
#pragma unroll
        for (int j = 0; j < 16; ++j) {
            int i = tid + 128 * j;
            int arr = i >> 9;
            int rem = i & 511;
            int r = rem >> 4, u = rem & 15;
            const __nv_bfloat16* gp =
                (arr == 0 ? Kh : arr == 1 ? Kl : arr == 2 ? Vh : Vl) +
                ((size_t)(s0 + r) * KVH + g) * HD + u * 8;
            uint32_t dst = sb + st * AT_STAGE + arr * 8192 + r * 256 + ((u ^ (r & 7)) << 4);
            asm volatile("cp.async.cg.shared.global [%0], [%1], 16;\n" :: "r"(dst), "l"(gp));
        }
        asm volatile("cp.async.commit_group;\n");
    };

    load_stage(0, s_lo);

    for (int tile = 0; tile < n_tiles; ++tile) {
        const int s0 = s_lo + tile * 32;
        if (tile + 1 < n_tiles) {
            load_stage((tile + 1) & 1, s0 + 32);
            asm volatile("cp.async.wait_group 1;\n");
        } else {
            asm volatile("cp.async.wait_group 0;\n");
        }
        __syncthreads();

        const uint32_t st = sb + (tile & 1) * AT_STAGE;

        // per-warp tile liveness: any (t, s) with s<=t, t-s<=WINDOW?
        const bool tile_needed = (s0 <= wrow_hi) && (s0 + 31 >= wrow_lo - WINDOW);
        if (tile_needed) {

        float S[4][4];
#pragma unroll
        for (int n = 0; n < 4; ++n)
#pragma unroll
            for (int j = 0; j < 4; ++j) S[n][j] = 0.f;

#pragma unroll
        for (int c = 0; c < 8; ++c) {
            uint32_t kh[2][4], kl[2][4];
#pragma unroll
            for (int p = 0; p < 2; ++p) {
                int row = p * 16 + (lane & 7) + 8 * ((lane >> 3) & 1);
                int u   = 2 * c + (lane >> 4);
                uint32_t off = row * 256 + ((u ^ (row & 7)) << 4);
                ldm_x4(kh[p], st + off);
                ldm_x4(kl[p], st + 8192 + off);
            }
#pragma unroll
            for (int n = 0; n < 4; ++n) {
                uint32_t bh[2] = { kh[n >> 1][n & 1], kh[n >> 1][(n & 1) + 2] };
                uint32_t bl[2] = { kl[n >> 1][n & 1], kl[n >> 1][(n & 1) + 2] };
                mma_bf16(S[n], qfh[c], bh);
                mma_bf16(S[n], qfh[c], bl);
                mma_bf16(S[n], qfl[c], bh);
            }
        }

        bool causal_safe = (s0 + 31 <= wrow_lo);
        bool window_safe = (s0 >= wrow_hi - WINDOW);
        if (!(causal_safe && window_safe)) {
#pragma unroll
            for (int n = 0; n < 4; ++n)
#pragma unroll
                for (int j = 0; j < 4; ++j) {
                    int s = s0 + 8 * n + 2 * tig + (j & 1);
                    int t = (j < 2) ? row0 : row0 + 8;
                    bool ok = (s <= t) && (t - s <= WINDOW);
                    if (!ok) S[n][j] = -1e30f;
                }
        }

        float mx0 = -1e30f, mx1 = -1e30f;
#pragma unroll
        for (int n = 0; n < 4; ++n) {
            mx0 = fmaxf(mx0, fmaxf(S[n][0], S[n][1]));
            mx1 = fmaxf(mx1, fmaxf(S[n][2], S[n][3]));
        }
        mx0 = fmaxf(mx0, __shfl_xor_sync(0xffffffffu, mx0, 1));
        mx0 = fmaxf(mx0, __shfl_xor_sync(0xffffffffu, mx0, 2));
        mx1 = fmaxf(mx1, __shfl_xor_sync(0xffffffffu, mx1, 1));
        mx1 = fmaxf(mx1, __shfl_xor_sync(0xffffffffu, mx1, 2));

        float mn0 = fmaxf(m0, mx0), mn1 = fmaxf(m1, mx1);
        float fac0 = __expf(m0 - mn0), fac1 = __expf(m1 - mn1);
        m0 = mn0; m1 = mn1;

        float rs0 = 0.f, rs1 = 0.f;
#pragma unroll
        for (int n = 0; n < 4; ++n) {
            S[n][0] = __expf(S[n][0] - mn0);
            S[n][1] = __expf(S[n][1] - mn0);
            S[n][2] = __expf(S[n][2] - mn1);
            S[n][3] = __expf(S[n][3] - mn1);
            rs0 += S[n][0] + S[n][1];
            rs1 += S[n][2] + S[n][3];
        }
        rs0 += __shfl_xor_sync(0xffffffffu, rs0, 1);
        rs0 += __shfl_xor_sync(0xffffffffu, rs0, 2);
        rs1 += __shfl_xor_sync(0xffffffffu, rs1, 1);
        rs1 += __shfl_xor_sync(0xffffffffu, rs1, 2);
        l0 = l0 * fac0 + rs0;
        l1 = l1 * fac1 + rs1;

#pragma unroll
        for (int n = 0; n < 16; ++n) {
            o[n][0] *= fac0; o[n][1] *= fac0;
            o[n][2] *= fac1; o[n][3] *= fac1;
        }

#pragma unroll
        for (int kc = 0; kc < 2; ++kc) {
            int j0 = 2 * kc, j1 = 2 * kc + 1;
            uint32_t pah[4], pal[4];
            pack_hilo(S[j0][0], S[j0][1], pah[0], pal[0]);
            pack_hilo(S[j0][2], S[j0][3], pah[1], pal[1]);
            pack_hilo(S[j1][0], S[j1][1], pah[2], pal[2]);
            pack_hilo(S[j1][2], S[j1][3], pah[3], pal[3]);
#pragma unroll
            for (int dp = 0; dp < 8; ++dp) {
                int row = kc * 16 + (lane & 7) + 8 * ((lane >> 3) & 1);
                int u   = 2 * dp + (lane >> 4);
                uint32_t off = row * 256 + ((u ^ (row & 7)) << 4);
                uint32_t vh[4], vl[4];
                ldm_x4_t(vh, st + 16384 + off);
                ldm_x4_t(vl, st + 24576 + off);
                uint32_t bh0[2] = { vh[0], vh[1] }, bh1[2] = { vh[2], vh[3] };
                uint32_t bl0[2] = { vl[0], vl[1] }, bl1[2] = { vl[2], vl[3] };
                mma_bf16(o[2 * dp],     pah, bh0);
                mma_bf16(o[2 * dp],     pah, bl0);
                mma_bf16(o[2 * dp],     pal, bh0);
                mma_bf16(o[2 * dp + 1], pah, bh1);
                mma_bf16(o[2 * dp + 1], pah, bl1);
                mma_bf16(o[2 * dp + 1], pal, bh1);
            }
        }

        }  // tile_needed
        __syncthreads();
    }

    float inv0 = 1.0f / l0, inv1 = 1.0f / l1;
#pragma unroll
    for (int n = 0; n < 16; ++n) {
        int d = 8 * n + 2 * tig;
        float a0 = o[n][0] * inv0, a1 = o[n][1] * inv0;
        float b0 = o[n][2] * inv1, b1 = o[n][3] * inv1;
        uint32_t h0, lo0, h1, lo1;
        pack_hilo(a0, a1, h0, lo0);
        pack_hilo(b0, b1, h1, lo1);
        size_t p0 = ((size_t)row0 * QH + h) * HD + d;
        size_t p1 = ((size_t)(row0 + 8) * QH + h) * HD + d;
        *reinterpret_cast<uint32_t*>(Oh + p0) = h0;
        *reinterpret_cast<uint32_t*>(Ol + p0) = lo0;
        *reinterpret_cast<uint32_t*>(Oh + p1) = h1;
        *reinterpret_cast<uint32_t*>(Ol + p1) = lo1;
    }
}

// ---------------------------------------------------------------------------
extern "C" void kernel_launch(void* const* d_in, const int* in_sizes, int n_in,
                              void* d_out, int out_size)
{
    const float* x  = (const float*)d_in[0];
    const float* wq = (const float*)d_in[1];
    const float* wk = (const float*)d_in[2];
    const float* wv = (const float*)d_in[3];
    const float* wo = (const float*)d_in[4];
    float* out = (float*)d_out;

    float* qkv;
    cudaGetSymbolAddress((void**)&qkv, g_qkv);

    __nv_bfloat16 *xh, *xl, *wch, *wcl, *woh, *wol;
    __nv_bfloat16 *qh, *ql, *kh, *kl, *vh, *vl, *atth, *attl;
    cudaGetSymbolAddress((void**)&xh,  g_xh);   cudaGetSymbolAddress((void**)&xl,  g_xl);
    cudaGetSymbolAddress((void**)&wch, g_wch);  cudaGetSymbolAddress((void**)&wcl, g_wcl);
    cudaGetSymbolAddress((void**)&woh, g_woh);  cudaGetSymbolAddress((void**)&wol, g_wol);
    cudaGetSymbolAddress((void**)&qh,  g_qh);   cudaGetSymbolAddress((void**)&ql,  g_ql);
    cudaGetSymbolAddress((void**)&kh,  g_kh);   cudaGetSymbolAddress((void**)&kl,  g_kl);
    cudaGetSymbolAddress((void**)&vh,  g_vh);   cudaGetSymbolAddress((void**)&vl,  g_vl);
    cudaGetSymbolAddress((void**)&atth, g_atth); cudaGetSymbolAddress((void**)&attl, g_attl);

    cudaFuncSetAttribute(gemm_bf16x3, cudaFuncAttributeMaxDynamicSharedMemorySize, 3 * GSTAGE);
    cudaFuncSetAttribute(attn_mma,    cudaFuncAttributeMaxDynamicSharedMemorySize, 2 * AT_STAGE);

    // #1: fused split of x and wq|wk|wv
    {
        int tot = T_LEN * HIDDEN / 4 + NC * HIDDEN / 4;
        split_xw_kernel<<<(tot + 255) / 256, 256>>>(x, wq, wk, wv, xh, xl, wch, wcl);
    }
    // #2: split wo (independent; early so later slots hold the interesting kernels)
    {
        int n4 = HIDDEN * QH * HD / 4;
        split_kernel<<<(n4 + 255) / 256, 256>>>(wo, woh, wol, n4);
    }
    // #3: fused QKV projection
    gemm_bf16x3<<<dim3(NC / 128, T_LEN / 128), 256, 3 * GSTAGE>>>(
        xh, xl, wch, wcl, qkv, T_LEN, NC, HIDDEN);
    // #4: fused RoPE+split (q,k) + V split  (profiling slot this round)
    {
        int tot = T_LEN * (QH + KVH) * (HD / 2) + T_LEN * KVH * HD / 4;
        rope_v_kernel<<<(tot + 255) / 256, 256>>>(qkv, qh, ql, kh, kl, vh, vl);
    }
    // #5: tensor-core attention
    attn_mma<<<dim3(T_LEN / 64, QH), 128, 2 * AT_STAGE>>>(
        qh, ql, kh, kl, vh, vl, atth, attl);
    // #6: output projection
    gemm_bf16x3<<<dim3(HIDDEN / 128, T_LEN / 128), 256, 3 * GSTAGE>>>(
        atth, attl, woh, wol, out, T_LEN, HIDDEN, QH * HD);
}